// round 15
// baseline (speedup 1.0000x reference)
#include <cuda_runtime.h>
#include <cuda_fp16.h>
#include <math.h>
#include <float.h>
#include <stdint.h>

#define BDIM 2
#define NSEG 256
#define HID 1024
#define HID2 512
#define NCLS 6
#define NROWS 512
#define NPAIRS 131072

// ---------------- scratch ----------------
__device__ __half g_a16[NROWS*HID];   // k-words PERMUTED: pos 2m<->word m, 2m+1<->word m+4 (per 8-word group)
__device__ __half g_b16[NROWS*HID];   // same permutation
__device__ float g_h1[NROWS*HID];
__device__ float g_h2[NROWS*HID2];
__device__ float g_hatp[NROWS*NCLS];
__device__ float g_loss1_terms[NROWS];
__device__ int   g_segy[NROWS];
__device__ float g_logit[NPAIRS*2];
__device__ float g_loss2_part[512];
__device__ int   g_ctr;
__device__ __half g_ws2t[HID2*HID];   // unpermuted [n][k]

// ---------------- helpers ----------------
__device__ __forceinline__ unsigned f2tf32(unsigned xbits) {
    unsigned r;
    asm("cvt.rna.tf32.f32 %0, %1;" : "=r"(r) : "r"(xbits));
    return r;
}
__device__ __forceinline__ void mma8(float* d, const unsigned* a, const unsigned* b) {
    asm volatile(
        "mma.sync.aligned.m16n8k8.row.col.f32.tf32.tf32.f32 "
        "{%0,%1,%2,%3}, {%4,%5,%6,%7}, {%8,%9}, {%0,%1,%2,%3};\n"
        : "+f"(d[0]), "+f"(d[1]), "+f"(d[2]), "+f"(d[3])
        : "r"(a[0]), "r"(a[1]), "r"(a[2]), "r"(a[3]), "r"(b[0]), "r"(b[1]));
}
__device__ __forceinline__ void mma16(float* d, const unsigned* a, const unsigned* b) {
    asm volatile(
        "mma.sync.aligned.m16n8k16.row.col.f32.f16.f16.f32 "
        "{%0,%1,%2,%3}, {%4,%5,%6,%7}, {%8,%9}, {%0,%1,%2,%3};\n"
        : "+f"(d[0]), "+f"(d[1]), "+f"(d[2]), "+f"(d[3])
        : "r"(a[0]), "r"(a[1]), "r"(a[2]), "r"(a[3]), "r"(b[0]), "r"(b[1]));
}
__device__ __forceinline__ void ldm4(unsigned* r, uint32_t addr) {
    asm volatile(
        "ldmatrix.sync.aligned.m8n8.x4.shared.b16 {%0,%1,%2,%3}, [%4];"
        : "=r"(r[0]), "=r"(r[1]), "=r"(r[2]), "=r"(r[3]) : "r"(addr));
}
__device__ __forceinline__ unsigned packh2(float lo, float hi) {
    __half2 h = __floats2half2_rn(lo, hi);
    return *reinterpret_cast<unsigned*>(&h);
}
__device__ __forceinline__ unsigned addrelu2(unsigned a, unsigned b) {
    __half2 r = __hmax2(__hadd2(*(__half2*)&a, *(__half2*)&b),
                        __float2half2_rn(0.f));
    return *reinterpret_cast<unsigned*>(&r);
}

#define SA_LD 36
#define SB_LD 136
#define GOF_A   0
#define GA_ST   18432
#define GOF_B   36864
#define GB_ST   17408
#define GSMEM   71680

// ---------------- tf32 GEMM body, cp.async double-buffered (proven) ---------
__device__ __forceinline__ void gemm_body(
    const float* __restrict__ A, int lda, const float* __restrict__ B, int ldb,
    float* __restrict__ C, __half* __restrict__ Ch, int ldc,
    const float* __restrict__ bias,
    int kbeg, int kend, int m0, int n0, int mode, char* smem)
{
    int tid = threadIdx.x;
    int lane = tid & 31, warp = tid >> 5;
    int wm = warp & 3, wn = warp >> 2;
    uint32_t u_a = (uint32_t)__cvta_generic_to_shared(smem + GOF_A);
    uint32_t u_b = (uint32_t)__cvta_generic_to_shared(smem + GOF_B);

    float acc[2][8][4];
    #pragma unroll
    for (int a = 0; a < 2; a++)
        #pragma unroll
        for (int b_ = 0; b_ < 8; b_++)
            #pragma unroll
            for (int c = 0; c < 4; c++) acc[a][b_][c] = 0.f;

    int nk = (kend - kbeg) >> 5;

    #define ISSUE_G(k0v, st) do {                                             \
        int _k0 = (k0v);                                                      \
        _Pragma("unroll")                                                     \
        for (int t = tid; t < 2048; t += 256) {                               \
            if (t < 1024) {                                                   \
                int row = t >> 3, cv = (t & 7) << 2;                          \
                asm volatile("cp.async.cg.shared.global [%0], [%1], 16;"      \
                    :: "r"(u_a + (st)*GA_ST + (row*SA_LD + cv)*4),            \
                       "l"(A + (long)(m0 + row)*lda + _k0 + cv) : "memory");  \
            } else {                                                          \
                int u = t - 1024;                                             \
                int row = u >> 5, cv = (u & 31) << 2;                         \
                asm volatile("cp.async.cg.shared.global [%0], [%1], 16;"      \
                    :: "r"(u_b + (st)*GB_ST + (row*SB_LD + cv)*4),            \
                       "l"(B + (long)(_k0 + row)*ldb + n0 + cv) : "memory");  \
            }                                                                 \
        }                                                                     \
        asm volatile("cp.async.commit_group;" ::: "memory");                  \
    } while (0)

    ISSUE_G(kbeg, 0);

    for (int it = 0; it < nk; it++) {
        __syncthreads();
        if (it + 1 < nk) {
            ISSUE_G(kbeg + ((it + 1) << 5), (it + 1) & 1);
            asm volatile("cp.async.wait_group 1;" ::: "memory");
        } else {
            asm volatile("cp.async.wait_group 0;" ::: "memory");
        }
        __syncthreads();

        const unsigned* sA = (const unsigned*)(smem + GOF_A + (it & 1) * GA_ST);
        const unsigned* sB = (const unsigned*)(smem + GOF_B + (it & 1) * GB_ST);
        #pragma unroll
        for (int ks = 0; ks < 4; ks++) {
            int k = ks << 3;
            unsigned af[2][4], bf[8][2];
            #pragma unroll
            for (int mi = 0; mi < 2; mi++) {
                int r = wm * 32 + mi * 16 + (lane >> 2);
                int c = k + (lane & 3);
                af[mi][0] = f2tf32(sA[r * SA_LD + c]);
                af[mi][1] = f2tf32(sA[(r + 8) * SA_LD + c]);
                af[mi][2] = f2tf32(sA[r * SA_LD + c + 4]);
                af[mi][3] = f2tf32(sA[(r + 8) * SA_LD + c + 4]);
            }
            #pragma unroll
            for (int ni = 0; ni < 8; ni++) {
                int c = wn * 64 + ni * 8 + (lane >> 2);
                int r = k + (lane & 3);
                bf[ni][0] = f2tf32(sB[r * SB_LD + c]);
                bf[ni][1] = f2tf32(sB[(r + 4) * SB_LD + c]);
            }
            #pragma unroll
            for (int mi = 0; mi < 2; mi++)
                #pragma unroll
                for (int ni = 0; ni < 8; ni++)
                    mma8(acc[mi][ni], af[mi], bf[ni]);
        }
    }
    #undef ISSUE_G

    #pragma unroll
    for (int mi = 0; mi < 2; mi++)
        #pragma unroll
        for (int ni = 0; ni < 8; ni++) {
            int r = m0 + wm * 32 + mi * 16 + (lane >> 2);
            int c = n0 + wn * 64 + ni * 8 + ((lane & 3) << 1);
            if (mode == 2) {
                atomicAdd(&C[(long)r * ldc + c],           acc[mi][ni][0]);
                atomicAdd(&C[(long)r * ldc + c + 1],       acc[mi][ni][1]);
                atomicAdd(&C[(long)(r + 8) * ldc + c],     acc[mi][ni][2]);
                atomicAdd(&C[(long)(r + 8) * ldc + c + 1], acc[mi][ni][3]);
            } else {
                float b0 = bias ? bias[c] : 0.f;
                float b1 = bias ? bias[c + 1] : 0.f;
                float v0 = acc[mi][ni][0] + b0, v1 = acc[mi][ni][1] + b1;
                float v2 = acc[mi][ni][2] + b0, v3 = acc[mi][ni][3] + b1;
                if (mode == 1) {
                    v0 = fmaxf(v0, 0.f); v1 = fmaxf(v1, 0.f);
                    v2 = fmaxf(v2, 0.f); v3 = fmaxf(v3, 0.f);
                    C[(long)r * ldc + c]       = v0; C[(long)r * ldc + c + 1]       = v1;
                    C[(long)(r + 8) * ldc + c] = v2; C[(long)(r + 8) * ldc + c + 1] = v3;
                } else {
                    // permuted k-word storage: word w -> pos (w&~7)|((w&3)<<1)|((w>>2)&1)
                    int w = c >> 1;
                    int wp = (w & ~7) | ((w & 3) << 1) | ((w >> 2) & 1);
                    *(unsigned*)&Ch[(long)r * ldc + wp * 2]       = packh2(v0, v1);
                    *(unsigned*)&Ch[(long)(r + 8) * ldc + wp * 2] = packh2(v2, v3);
                }
            }
        }
}

// h1 / a16 / b16 fused (R12 topology): 24 roles x 4 m-tiles = 96 CTAs.
__global__ __launch_bounds__(256)
void gemm3(const float* __restrict__ agg,
           const float* __restrict__ W1, const float* __restrict__ b1,
           const float* __restrict__ Ws1, const float* __restrict__ bs1)
{
    extern __shared__ char smem[];
    int tn = blockIdx.x % 24;
    int m0 = (blockIdx.x / 24) << 7;
    int grp = tn >> 3;
    int n0 = (tn & 7) << 7;
    if (grp == 0)
        gemm_body(agg, 512, W1, 1024, g_h1, (half*)0, 1024, b1, 0, 512, m0, n0, 1, smem);
    else if (grp == 1)
        gemm_body(agg, 512, Ws1, 1024, (float*)0, g_a16, 1024, bs1, 0, 512, m0, n0, 3, smem);
    else
        gemm_body(agg, 512, Ws1 + 512 * 1024, 1024, (float*)0, g_b16, 1024,
                  (const float*)0, 0, 512, m0, n0, 3, smem);
}

__global__ __launch_bounds__(256)
void gemm_h2(const float* __restrict__ W2)
{
    extern __shared__ char smem[];
    int t = blockIdx.x & 15;
    int ks = blockIdx.x >> 4;
    int m0 = (t >> 2) << 7;
    int n0 = (t & 3) << 7;
    gemm_body(g_h1, 1024, W2, 512, g_h2, (half*)0, 512, (const float*)0,
              ks * 128, ks * 128 + 128, m0, n0, 2, smem);
}

// ---------------- fused: zero bufs + counter + Ws2 transpose->fp16 ----------
__global__ void zeroprep(const float* __restrict__ Ws2)
{
    int tid = threadIdx.x;
    if (blockIdx.x < 32) {
        if (blockIdx.x == 0 && tid == 0) g_ctr = 0;
        int base = blockIdx.x * 16384 + tid;
        #pragma unroll
        for (int r = 0; r < 64; r++) {
            int i = base + r * 256;
            if (i < NPAIRS * 2) g_logit[i] = 0.f;
            else g_h2[i - NPAIRS * 2] = 0.f;
        }
    } else {
        __shared__ float tile[32][33];
        int tx = tid & 31, ty = tid >> 5;
        int tbase = (blockIdx.x - 32) * 16;
        for (int t = 0; t < 16; t++) {
            int bx = (tbase + t) & 15;
            int by = (tbase + t) >> 4;
            #pragma unroll
            for (int r = 0; r < 32; r += 8)
                tile[ty + r][tx] = Ws2[(long)(by * 32 + ty + r) * HID2 + bx * 32 + tx];
            __syncthreads();
            #pragma unroll
            for (int r = 0; r < 32; r += 8)
                g_ws2t[(long)(bx * 32 + ty + r) * HID + by * 32 + tx] =
                    __float2half_rn(tile[tx][ty + r]);
            __syncthreads();
        }
    }
}

// ---------------- per-segment epilogue ----------------
__global__ void seg_epilogue(const float* __restrict__ W3,
                             const float* __restrict__ b3,
                             const float* __restrict__ b2,
                             const int* __restrict__ yw)
{
    int row = blockIdx.x;
    int lane = threadIdx.x;
    float s[6] = {0.f, 0.f, 0.f, 0.f, 0.f, 0.f};
    const float* hrow = g_h2 + (long)row * HID2;
    for (int k = lane; k < HID2; k += 32) {
        float h = fmaxf(hrow[k] + b2[k], 0.f);
        const float* w = W3 + k * 6;
        #pragma unroll
        for (int c = 0; c < 6; c++) s[c] += h * w[c];
    }
    #pragma unroll
    for (int off = 16; off > 0; off >>= 1)
        #pragma unroll
        for (int c = 0; c < 6; c++) s[c] += __shfl_xor_sync(0xffffffffu, s[c], off);

    if (lane == 0) {
        float l[6], m = -FLT_MAX;
        #pragma unroll
        for (int c = 0; c < 6; c++) { l[c] = s[c] + b3[c]; m = fmaxf(m, l[c]); }
        float se = 0.f;
        #pragma unroll
        for (int c = 0; c < 6; c++) se += expf(l[c] - m);
        float lse = m + logf(se);
        #pragma unroll
        for (int c = 0; c < 6; c++) g_hatp[row * 6 + c] = expf(l[c] - lse);

        int sum12 = 0;
        #pragma unroll
        for (int w = 0; w < 12; w++) sum12 += yw[w];
        int is64 = (sum12 == 1);
        int arg = 0;
        int bv = is64 ? yw[(row * 6) * 2] : yw[row * 6];
        #pragma unroll
        for (int c = 1; c < 6; c++) {
            int v = is64 ? yw[(row * 6 + c) * 2] : yw[row * 6 + c];
            if (v > bv) { bv = v; arg = c; }
        }
        g_segy[row] = arg;
        g_loss1_terms[row] = -(l[arg] - lse);
    }
}

// ---------------- fp16 pairwise GEMM: depth-3, issue-after-sync -------------
#define POF_B    0                        // 3 x 18432 = 55296
#define POF_A2   55296                    // 3 x 2560  = 7680 (16 rows x 160B)
#define POF_B2   62976                    // 3 x 1280  = 3840 (8 rows x 160B)
#define POF_BIAS 66816
#define POF_W3   67328
#define POF_LP   68352
#define PSMEM    69376

__global__ void __launch_bounds__(256, 2)
pair_fp16(const float* __restrict__ bs2, const float* __restrict__ Ws3)
{
    extern __shared__ char smem[];
    float* sBias = (float*)(smem + POF_BIAS);
    float* sW3   = (float*)(smem + POF_W3);
    float* sLP   = (float*)(smem + POF_LP);

    uint32_t u_b  = (uint32_t)__cvta_generic_to_shared(smem + POF_B);
    uint32_t u_a2 = (uint32_t)__cvta_generic_to_shared(smem + POF_A2);
    uint32_t u_b2 = (uint32_t)__cvta_generic_to_shared(smem + POF_B2);

    int tid = threadIdx.x, lane = tid & 31, warp = tid >> 5;
    int wm = warp & 3, wn = warp >> 2;
    int id = blockIdx.x;
    int nb = id & 3;
    int jt = (id >> 2) & 31;
    int it = (id >> 7) & 15;
    int bi = id >> 11;
    int i0 = it << 4, j0 = jt << 3, n0 = nb << 7;

    if (tid < 128) {
        sBias[tid] = bs2[n0 + tid];
        sW3[tid * 2]     = Ws3[(n0 + tid) * 2];
        sW3[tid * 2 + 1] = Ws3[(n0 + tid) * 2 + 1];
        sLP[tid] = 0.f; sLP[tid + 128] = 0.f;
    }

    const __half* ga = g_a16 + (long)(bi * 256 + i0) * HID;
    const __half* gb = g_b16 + (long)(bi * 256 + j0) * HID;
    const __half* wsrc = g_ws2t + (long)n0 * HID;

    float acc[2][8][4];
    #pragma unroll
    for (int a = 0; a < 2; a++)
        #pragma unroll
        for (int b_ = 0; b_ < 8; b_++)
            #pragma unroll
            for (int c = 0; c < 4; c++) acc[a][b_][c] = 0.f;

    #define ISSUE(cc, bb) do {                                                \
        int k0h = (cc) * 64;                                                  \
        _Pragma("unroll")                                                     \
        for (int t = tid; t < 1216; t += 256) {                               \
            if (t < 1024) {                                                   \
                int n = t >> 3, seg = t & 7;                                  \
                asm volatile("cp.async.cg.shared.global [%0], [%1], 16;"      \
                    :: "r"(u_b + (bb)*18432 + n*144 + seg*16),                \
                       "l"(wsrc + (long)n*HID + k0h + seg*8) : "memory");     \
            } else if (t < 1152) {                                            \
                int u = t - 1024; int r = u >> 3, seg = u & 7;                \
                asm volatile("cp.async.ca.shared.global [%0], [%1], 16;"      \
                    :: "r"(u_a2 + (bb)*2560 + r*160 + seg*16),                \
                       "l"(ga + (long)r*HID + k0h + seg*8) : "memory");       \
            } else {                                                          \
                int u = t - 1152; int r = u >> 3, seg = u & 7;                \
                asm volatile("cp.async.ca.shared.global [%0], [%1], 16;"      \
                    :: "r"(u_b2 + (bb)*1280 + r*160 + seg*16),                \
                       "l"(gb + (long)r*HID + k0h + seg*8) : "memory");       \
            }                                                                 \
        }                                                                     \
        asm volatile("cp.async.commit_group;" ::: "memory");                  \
    } while (0)

    // prologue: chunks 0,1 in flight
    ISSUE(0, 0);
    ISSUE(1, 1);

    int c0 = lane & 3;
    int jl = lane >> 2;
    uint32_t ldm_off = (uint32_t)(wn * 64 + ((lane >> 4) << 3) + (lane & 7)) * 144u
                     + (uint32_t)((lane >> 3) & 1) * 16u;

    for (int c = 0; c < 16; c++) {
        // own chunk-c copies done (1 newer group may remain in flight)...
        if (c < 15) asm volatile("cp.async.wait_group 1;" ::: "memory");
        else        asm volatile("cp.async.wait_group 0;" ::: "memory");
        // ...barrier: everyone's chunk-c data visible; all chunk c-1 reads
        // ordered before the issue below overwrites slot (c+2)%3.
        __syncthreads();

        // issue EARLY (before compute): two copies in flight during compute c
        if (c + 2 < 16) ISSUE(c + 2, (c + 2) % 3);

        int buf = c % 3;
        const unsigned* A2 = (const unsigned*)(smem + POF_A2 + buf * 2560);
        const unsigned* B2 = (const unsigned*)(smem + POF_B2 + buf * 1280);
        uint32_t bb_base = u_b + buf * 18432 + ldm_off;

        #pragma unroll
        for (int ks = 0; ks < 4; ks++) {
            uint2 bv = *(const uint2*)(B2 + jl * 40 + ks * 8 + 2 * c0);
            unsigned af[2][4], bf[8][2];
            #pragma unroll
            for (int mi = 0; mi < 2; mi++) {
                int base = (wm * 4 + mi * 2) * 40 + ks * 8 + 2 * c0;
                uint2 a01 = *(const uint2*)(A2 + base);
                uint2 a23 = *(const uint2*)(A2 + base + 40);
                af[mi][0] = addrelu2(a01.x, bv.x);
                af[mi][1] = addrelu2(a23.x, bv.x);
                af[mi][2] = addrelu2(a01.y, bv.y);
                af[mi][3] = addrelu2(a23.y, bv.y);
            }
            #pragma unroll
            for (int g = 0; g < 4; g++) {
                unsigned rr[4];
                ldm4(rr, bb_base + (uint32_t)g * 2304u + (uint32_t)ks * 32u);
                bf[g * 2][0]     = rr[0];
                bf[g * 2][1]     = rr[1];
                bf[g * 2 + 1][0] = rr[2];
                bf[g * 2 + 1][1] = rr[3];
            }
            #pragma unroll
            for (int mi = 0; mi < 2; mi++)
                #pragma unroll
                for (int nt = 0; nt < 8; nt++)
                    mma16(acc[mi][nt], af[mi], bf[nt]);
        }
    }
    __syncthreads();

    // ---- epilogue ----
    float lp[2][2][2];
    #pragma unroll
    for (int mi = 0; mi < 2; mi++)
        #pragma unroll
        for (int h = 0; h < 2; h++) { lp[mi][h][0] = 0.f; lp[mi][h][1] = 0.f; }

    #pragma unroll
    for (int mi = 0; mi < 2; mi++)
        #pragma unroll
        for (int nt = 0; nt < 8; nt++) {
            int cl = wn * 64 + nt * 8 + ((lane & 3) << 1);
            float bz0 = sBias[cl], bz1 = sBias[cl + 1];
            float w00 = sW3[cl * 2],       w01 = sW3[cl * 2 + 1];
            float w10 = sW3[(cl + 1) * 2], w11 = sW3[(cl + 1) * 2 + 1];
            float z0 = fmaxf(acc[mi][nt][0] + bz0, 0.f);
            float z1 = fmaxf(acc[mi][nt][1] + bz1, 0.f);
            float z2 = fmaxf(acc[mi][nt][2] + bz0, 0.f);
            float z3 = fmaxf(acc[mi][nt][3] + bz1, 0.f);
            lp[mi][0][0] += z0 * w00 + z1 * w10;
            lp[mi][0][1] += z0 * w01 + z1 * w11;
            lp[mi][1][0] += z2 * w00 + z3 * w10;
            lp[mi][1][1] += z2 * w01 + z3 * w11;
        }
    #pragma unroll
    for (int off = 1; off < 4; off <<= 1)
        #pragma unroll
        for (int mi = 0; mi < 2; mi++)
            #pragma unroll
            for (int h = 0; h < 2; h++) {
                lp[mi][h][0] += __shfl_xor_sync(0xffffffffu, lp[mi][h][0], off);
                lp[mi][h][1] += __shfl_xor_sync(0xffffffffu, lp[mi][h][1], off);
            }
    if ((lane & 3) == 0) {
        #pragma unroll
        for (int mi = 0; mi < 2; mi++) {
            int p = wm * 32 + mi * 16 + (lane >> 2);
            atomicAdd(&sLP[p * 2],           lp[mi][0][0]);
            atomicAdd(&sLP[p * 2 + 1],       lp[mi][0][1]);
            atomicAdd(&sLP[(p + 8) * 2],     lp[mi][1][0]);
            atomicAdd(&sLP[(p + 8) * 2 + 1], lp[mi][1][1]);
        }
    }
    __syncthreads();
    {
        int p = tid >> 1, s = tid & 1;
        int i = i0 + (p >> 3), j = j0 + (p & 7);
        long flat = (long)(bi * 256 + i) * 256 + j;
        atomicAdd(&g_logit[flat * 2 + s], sLP[tid]);
    }
    #undef ISSUE
}

// ---------------- fused row epilogue + last-block loss finalize -------------
__global__ void epi_row(const float* __restrict__ bs3, float* __restrict__ out)
{
    int row = blockIdx.x;
    int tid = threadIdx.x;
    int bi = row >> 8;
    int idx = row * 256 + tid;

    float l0 = g_logit[idx * 2]     + bs3[0];
    float l1 = g_logit[idx * 2 + 1] + bs3[1];
    float m = fmaxf(l0, l1);
    float e0 = expf(l0 - m), e1 = expf(l1 - m);
    float lse = m + logf(e0 + e1);
    float lq0 = l0 - lse, lq1 = l1 - lse;
    float q1 = expf(lq1);
    float sel = (g_segy[row] == g_segy[(bi << 8) + tid]) ? lq1 : lq0;

    __shared__ float sred[256][6];
    __shared__ float red[256];
    __shared__ int slast;
    const float* hp = g_hatp + (long)((bi << 8) + tid) * 6;
    #pragma unroll
    for (int c = 0; c < 6; c++) sred[tid][c] = q1 * hp[c];
    red[tid] = sel;
    __syncthreads();
    for (int s = 128; s > 0; s >>= 1) {
        if (tid < s) {
            #pragma unroll
            for (int c = 0; c < 6; c++) sred[tid][c] += sred[tid + s][c];
            red[tid] += red[tid + s];
        }
        __syncthreads();
    }
    if (tid < 6) out[1 + row * 6 + tid] = g_hatp[row * 6 + tid];
    if (tid == 0) {
        g_loss2_part[row] = red[0];
        float t = 0.f;
        #pragma unroll
        for (int c = 0; c < 6; c++) t += sred[0][c];
        #pragma unroll
        for (int c = 0; c < 6; c++) out[3073 + row * 6 + c] = sred[0][c] / t;
        __threadfence();
        slast = (atomicAdd(&g_ctr, 1) == 511);
    }
    if (tid == 32) out[6145 + row] = (float)g_segy[row];
    __syncthreads();
    if (slast) {
        __threadfence();
        float r1 = g_loss1_terms[tid] + g_loss1_terms[tid + 256];
        float r2 = g_loss2_part[tid] + g_loss2_part[tid + 256];
        red[tid] = r2;
        sred[tid][0] = r1;
        __syncthreads();
        for (int s = 128; s > 0; s >>= 1) {
            if (tid < s) { sred[tid][0] += sred[tid + s][0]; red[tid] += red[tid + s]; }
            __syncthreads();
        }
        if (tid == 0) out[0] = sred[0][0] / 512.0f - red[0] / 131072.0f;
    }
}

// ---------------- launch (R12-proven topology) ----------------
extern "C" void kernel_launch(void* const* d_in, const int* in_sizes, int n_in,
                              void* d_out, int out_size)
{
    const float* agg = (const float*)d_in[0];
    const int*   yw  = (const int*)d_in[1];
    const float* W1  = (const float*)d_in[2];
    const float* b1  = (const float*)d_in[3];
    const float* W2  = (const float*)d_in[4];
    const float* b2  = (const float*)d_in[5];
    const float* W3  = (const float*)d_in[6];
    const float* b3  = (const float*)d_in[7];
    const float* Ws1 = (const float*)d_in[8];
    const float* bs1 = (const float*)d_in[9];
    const float* Ws2 = (const float*)d_in[10];
    const float* bs2 = (const float*)d_in[11];
    const float* Ws3 = (const float*)d_in[12];
    const float* bs3 = (const float*)d_in[13];
    float* out = (float*)d_out;

    static cudaStream_t s1;
    static cudaEvent_t evF, evG, evZ, evS;
    static int cfg_done = 0;
    if (!cfg_done) {
        cudaFuncSetAttribute(pair_fp16,
                             cudaFuncAttributeMaxDynamicSharedMemorySize, PSMEM);
        cudaFuncSetAttribute(gemm3,
                             cudaFuncAttributeMaxDynamicSharedMemorySize, GSMEM);
        cudaFuncSetAttribute(gemm_h2,
                             cudaFuncAttributeMaxDynamicSharedMemorySize, GSMEM);
        cudaStreamCreateWithFlags(&s1, cudaStreamNonBlocking);
        cudaEventCreateWithFlags(&evF, cudaEventDisableTiming);
        cudaEventCreateWithFlags(&evG, cudaEventDisableTiming);
        cudaEventCreateWithFlags(&evZ, cudaEventDisableTiming);
        cudaEventCreateWithFlags(&evS, cudaEventDisableTiming);
        cfg_done = 1;
    }

    cudaEventRecord(evF, 0);
    cudaStreamWaitEvent(s1, evF, 0);

    zeroprep<<<64, 256, 0, s1>>>(Ws2);
    cudaEventRecord(evZ, s1);

    gemm3<<<96, 256, GSMEM>>>(agg, W1, b1, Ws1, bs1);
    cudaEventRecord(evG, 0);

    cudaStreamWaitEvent(s1, evG, 0);
    gemm_h2<<<128, 256, GSMEM, s1>>>(W2);
    seg_epilogue<<<512, 32, 0, s1>>>(W3, b3, b2, yw);
    cudaEventRecord(evS, s1);

    cudaStreamWaitEvent(0, evZ, 0);
    pair_fp16<<<4096, 256, PSMEM>>>(bs2, Ws3);

    cudaStreamWaitEvent(0, evS, 0);
    epi_row<<<512, 256>>>(bs3, out);
}

// round 16
// speedup vs baseline: 1.0445x; 1.0445x over previous
#include <cuda_runtime.h>
#include <cuda_fp16.h>
#include <math.h>
#include <float.h>
#include <stdint.h>

#define BDIM 2
#define NSEG 256
#define HID 1024
#define HID2 512
#define NCLS 6
#define NROWS 512
#define NPAIRS 131072

// ---------------- scratch ----------------
__device__ __half g_a16[NROWS*HID];   // k-words PERMUTED: pos 2m<->word m, 2m+1<->word m+4 (per 8-word group)
__device__ __half g_b16[NROWS*HID];   // same permutation
__device__ float g_h1[NROWS*HID];
__device__ float g_h2[NROWS*HID2];
__device__ float g_hatp[NROWS*NCLS];
__device__ float g_loss1_terms[NROWS];
__device__ int   g_segy[NROWS];
__device__ float g_logit[NPAIRS*2];
__device__ float g_loss2_part[512];
__device__ int   g_ctr;
__device__ __half g_ws2t[HID2*HID];   // unpermuted [n][k]

// ---------------- helpers ----------------
__device__ __forceinline__ unsigned f2tf32(unsigned xbits) {
    unsigned r;
    asm("cvt.rna.tf32.f32 %0, %1;" : "=r"(r) : "r"(xbits));
    return r;
}
__device__ __forceinline__ void mma8(float* d, const unsigned* a, const unsigned* b) {
    asm volatile(
        "mma.sync.aligned.m16n8k8.row.col.f32.tf32.tf32.f32 "
        "{%0,%1,%2,%3}, {%4,%5,%6,%7}, {%8,%9}, {%0,%1,%2,%3};\n"
        : "+f"(d[0]), "+f"(d[1]), "+f"(d[2]), "+f"(d[3])
        : "r"(a[0]), "r"(a[1]), "r"(a[2]), "r"(a[3]), "r"(b[0]), "r"(b[1]));
}
__device__ __forceinline__ void mma16(float* d, const unsigned* a, const unsigned* b) {
    asm volatile(
        "mma.sync.aligned.m16n8k16.row.col.f32.f16.f16.f32 "
        "{%0,%1,%2,%3}, {%4,%5,%6,%7}, {%8,%9}, {%0,%1,%2,%3};\n"
        : "+f"(d[0]), "+f"(d[1]), "+f"(d[2]), "+f"(d[3])
        : "r"(a[0]), "r"(a[1]), "r"(a[2]), "r"(a[3]), "r"(b[0]), "r"(b[1]));
}
__device__ __forceinline__ void ldm4(unsigned* r, uint32_t addr) {
    asm volatile(
        "ldmatrix.sync.aligned.m8n8.x4.shared.b16 {%0,%1,%2,%3}, [%4];"
        : "=r"(r[0]), "=r"(r[1]), "=r"(r[2]), "=r"(r[3]) : "r"(addr));
}
__device__ __forceinline__ unsigned packh2(float lo, float hi) {
    __half2 h = __floats2half2_rn(lo, hi);
    return *reinterpret_cast<unsigned*>(&h);
}
__device__ __forceinline__ unsigned addrelu2(unsigned a, unsigned b) {
    __half2 r = __hmax2(__hadd2(*(__half2*)&a, *(__half2*)&b),
                        __float2half2_rn(0.f));
    return *reinterpret_cast<unsigned*>(&r);
}

#define SA_LD 36
#define SB_LD 136
#define GOF_A   0
#define GA_ST   18432
#define GOF_B   36864
#define GB_ST   17408
#define GSMEM   71680

// ---------------- tf32 GEMM body, cp.async double-buffered (proven) ---------
__device__ __forceinline__ void gemm_body(
    const float* __restrict__ A, int lda, const float* __restrict__ B, int ldb,
    float* __restrict__ C, __half* __restrict__ Ch, int ldc,
    const float* __restrict__ bias,
    int kbeg, int kend, int m0, int n0, int mode, char* smem)
{
    int tid = threadIdx.x;
    int lane = tid & 31, warp = tid >> 5;
    int wm = warp & 3, wn = warp >> 2;
    uint32_t u_a = (uint32_t)__cvta_generic_to_shared(smem + GOF_A);
    uint32_t u_b = (uint32_t)__cvta_generic_to_shared(smem + GOF_B);

    float acc[2][8][4];
    #pragma unroll
    for (int a = 0; a < 2; a++)
        #pragma unroll
        for (int b_ = 0; b_ < 8; b_++)
            #pragma unroll
            for (int c = 0; c < 4; c++) acc[a][b_][c] = 0.f;

    int nk = (kend - kbeg) >> 5;

    #define ISSUE_G(k0v, st) do {                                             \
        int _k0 = (k0v);                                                      \
        _Pragma("unroll")                                                     \
        for (int t = tid; t < 2048; t += 256) {                               \
            if (t < 1024) {                                                   \
                int row = t >> 3, cv = (t & 7) << 2;                          \
                asm volatile("cp.async.cg.shared.global [%0], [%1], 16;"      \
                    :: "r"(u_a + (st)*GA_ST + (row*SA_LD + cv)*4),            \
                       "l"(A + (long)(m0 + row)*lda + _k0 + cv) : "memory");  \
            } else {                                                          \
                int u = t - 1024;                                             \
                int row = u >> 5, cv = (u & 31) << 2;                         \
                asm volatile("cp.async.cg.shared.global [%0], [%1], 16;"      \
                    :: "r"(u_b + (st)*GB_ST + (row*SB_LD + cv)*4),            \
                       "l"(B + (long)(_k0 + row)*ldb + n0 + cv) : "memory");  \
            }                                                                 \
        }                                                                     \
        asm volatile("cp.async.commit_group;" ::: "memory");                  \
    } while (0)

    ISSUE_G(kbeg, 0);

    for (int it = 0; it < nk; it++) {
        __syncthreads();
        if (it + 1 < nk) {
            ISSUE_G(kbeg + ((it + 1) << 5), (it + 1) & 1);
            asm volatile("cp.async.wait_group 1;" ::: "memory");
        } else {
            asm volatile("cp.async.wait_group 0;" ::: "memory");
        }
        __syncthreads();

        const unsigned* sA = (const unsigned*)(smem + GOF_A + (it & 1) * GA_ST);
        const unsigned* sB = (const unsigned*)(smem + GOF_B + (it & 1) * GB_ST);
        #pragma unroll
        for (int ks = 0; ks < 4; ks++) {
            int k = ks << 3;
            unsigned af[2][4], bf[8][2];
            #pragma unroll
            for (int mi = 0; mi < 2; mi++) {
                int r = wm * 32 + mi * 16 + (lane >> 2);
                int c = k + (lane & 3);
                af[mi][0] = f2tf32(sA[r * SA_LD + c]);
                af[mi][1] = f2tf32(sA[(r + 8) * SA_LD + c]);
                af[mi][2] = f2tf32(sA[r * SA_LD + c + 4]);
                af[mi][3] = f2tf32(sA[(r + 8) * SA_LD + c + 4]);
            }
            #pragma unroll
            for (int ni = 0; ni < 8; ni++) {
                int c = wn * 64 + ni * 8 + (lane >> 2);
                int r = k + (lane & 3);
                bf[ni][0] = f2tf32(sB[r * SB_LD + c]);
                bf[ni][1] = f2tf32(sB[(r + 4) * SB_LD + c]);
            }
            #pragma unroll
            for (int mi = 0; mi < 2; mi++)
                #pragma unroll
                for (int ni = 0; ni < 8; ni++)
                    mma8(acc[mi][ni], af[mi], bf[ni]);
        }
    }
    #undef ISSUE_G

    #pragma unroll
    for (int mi = 0; mi < 2; mi++)
        #pragma unroll
        for (int ni = 0; ni < 8; ni++) {
            int r = m0 + wm * 32 + mi * 16 + (lane >> 2);
            int c = n0 + wn * 64 + ni * 8 + ((lane & 3) << 1);
            if (mode == 2) {
                atomicAdd(&C[(long)r * ldc + c],           acc[mi][ni][0]);
                atomicAdd(&C[(long)r * ldc + c + 1],       acc[mi][ni][1]);
                atomicAdd(&C[(long)(r + 8) * ldc + c],     acc[mi][ni][2]);
                atomicAdd(&C[(long)(r + 8) * ldc + c + 1], acc[mi][ni][3]);
            } else {
                float b0 = bias ? bias[c] : 0.f;
                float b1 = bias ? bias[c + 1] : 0.f;
                float v0 = acc[mi][ni][0] + b0, v1 = acc[mi][ni][1] + b1;
                float v2 = acc[mi][ni][2] + b0, v3 = acc[mi][ni][3] + b1;
                if (mode == 1) {
                    v0 = fmaxf(v0, 0.f); v1 = fmaxf(v1, 0.f);
                    v2 = fmaxf(v2, 0.f); v3 = fmaxf(v3, 0.f);
                    C[(long)r * ldc + c]       = v0; C[(long)r * ldc + c + 1]       = v1;
                    C[(long)(r + 8) * ldc + c] = v2; C[(long)(r + 8) * ldc + c + 1] = v3;
                } else {
                    // permuted k-word storage: word w -> pos (w&~7)|((w&3)<<1)|((w>>2)&1)
                    int w = c >> 1;
                    int wp = (w & ~7) | ((w & 3) << 1) | ((w >> 2) & 1);
                    *(unsigned*)&Ch[(long)r * ldc + wp * 2]       = packh2(v0, v1);
                    *(unsigned*)&Ch[(long)(r + 8) * ldc + wp * 2] = packh2(v2, v3);
                }
            }
        }
}

// h1 / a16 / b16 fused (R12 topology): 24 roles x 4 m-tiles = 96 CTAs.
__global__ __launch_bounds__(256)
void gemm3(const float* __restrict__ agg,
           const float* __restrict__ W1, const float* __restrict__ b1,
           const float* __restrict__ Ws1, const float* __restrict__ bs1)
{
    extern __shared__ char smem[];
    int tn = blockIdx.x % 24;
    int m0 = (blockIdx.x / 24) << 7;
    int grp = tn >> 3;
    int n0 = (tn & 7) << 7;
    if (grp == 0)
        gemm_body(agg, 512, W1, 1024, g_h1, (half*)0, 1024, b1, 0, 512, m0, n0, 1, smem);
    else if (grp == 1)
        gemm_body(agg, 512, Ws1, 1024, (float*)0, g_a16, 1024, bs1, 0, 512, m0, n0, 3, smem);
    else
        gemm_body(agg, 512, Ws1 + 512 * 1024, 1024, (float*)0, g_b16, 1024,
                  (const float*)0, 0, 512, m0, n0, 3, smem);
}

__global__ __launch_bounds__(256)
void gemm_h2(const float* __restrict__ W2)
{
    extern __shared__ char smem[];
    int t = blockIdx.x & 15;
    int ks = blockIdx.x >> 4;
    int m0 = (t >> 2) << 7;
    int n0 = (t & 3) << 7;
    gemm_body(g_h1, 1024, W2, 512, g_h2, (half*)0, 512, (const float*)0,
              ks * 128, ks * 128 + 128, m0, n0, 2, smem);
}

// ---------------- fused: zero bufs + counter + Ws2 transpose->fp16 ----------
__global__ void zeroprep(const float* __restrict__ Ws2)
{
    int tid = threadIdx.x;
    if (blockIdx.x < 32) {
        if (blockIdx.x == 0 && tid == 0) g_ctr = 0;
        int base = blockIdx.x * 16384 + tid;
        #pragma unroll
        for (int r = 0; r < 64; r++) {
            int i = base + r * 256;
            if (i < NPAIRS * 2) g_logit[i] = 0.f;
            else g_h2[i - NPAIRS * 2] = 0.f;
        }
    } else {
        __shared__ float tile[32][33];
        int tx = tid & 31, ty = tid >> 5;
        int tbase = (blockIdx.x - 32) * 16;
        for (int t = 0; t < 16; t++) {
            int bx = (tbase + t) & 15;
            int by = (tbase + t) >> 4;
            #pragma unroll
            for (int r = 0; r < 32; r += 8)
                tile[ty + r][tx] = Ws2[(long)(by * 32 + ty + r) * HID2 + bx * 32 + tx];
            __syncthreads();
            #pragma unroll
            for (int r = 0; r < 32; r += 8)
                g_ws2t[(long)(bx * 32 + ty + r) * HID + by * 32 + tx] =
                    __float2half_rn(tile[tx][ty + r]);
            __syncthreads();
        }
    }
}

// ---------------- per-segment epilogue ----------------
__global__ void seg_epilogue(const float* __restrict__ W3,
                             const float* __restrict__ b3,
                             const float* __restrict__ b2,
                             const int* __restrict__ yw)
{
    int row = blockIdx.x;
    int lane = threadIdx.x;
    float s[6] = {0.f, 0.f, 0.f, 0.f, 0.f, 0.f};
    const float* hrow = g_h2 + (long)row * HID2;
    for (int k = lane; k < HID2; k += 32) {
        float h = fmaxf(hrow[k] + b2[k], 0.f);
        const float* w = W3 + k * 6;
        #pragma unroll
        for (int c = 0; c < 6; c++) s[c] += h * w[c];
    }
    #pragma unroll
    for (int off = 16; off > 0; off >>= 1)
        #pragma unroll
        for (int c = 0; c < 6; c++) s[c] += __shfl_xor_sync(0xffffffffu, s[c], off);

    if (lane == 0) {
        float l[6], m = -FLT_MAX;
        #pragma unroll
        for (int c = 0; c < 6; c++) { l[c] = s[c] + b3[c]; m = fmaxf(m, l[c]); }
        float se = 0.f;
        #pragma unroll
        for (int c = 0; c < 6; c++) se += expf(l[c] - m);
        float lse = m + logf(se);
        #pragma unroll
        for (int c = 0; c < 6; c++) g_hatp[row * 6 + c] = expf(l[c] - lse);

        int sum12 = 0;
        #pragma unroll
        for (int w = 0; w < 12; w++) sum12 += yw[w];
        int is64 = (sum12 == 1);
        int arg = 0;
        int bv = is64 ? yw[(row * 6) * 2] : yw[row * 6];
        #pragma unroll
        for (int c = 1; c < 6; c++) {
            int v = is64 ? yw[(row * 6 + c) * 2] : yw[row * 6 + c];
            if (v > bv) { bv = v; arg = c; }
        }
        g_segy[row] = arg;
        g_loss1_terms[row] = -(l[arg] - lse);
    }
}

// ---------------- fp16 pairwise GEMM: ldmatrix B + uint2 cache loads --------
// a/b caches: 160B pitch (40 u32), permuted k-words -> (c0,c0+4) adjacent.
#define POF_B    0                        // 3 x 18432 = 55296
#define POF_A2   55296                    // 3 x 2560  = 7680 (16 rows x 160B)
#define POF_B2   62976                    // 3 x 1280  = 3840 (8 rows x 160B)
#define POF_BIAS 66816
#define POF_W3   67328
#define POF_LP   68352
#define PSMEM    69376

__global__ void __launch_bounds__(256, 2)
pair_fp16(const float* __restrict__ bs2, const float* __restrict__ Ws3)
{
    extern __shared__ char smem[];
    float* sBias = (float*)(smem + POF_BIAS);
    float* sW3   = (float*)(smem + POF_W3);
    float* sLP   = (float*)(smem + POF_LP);

    uint32_t u_b  = (uint32_t)__cvta_generic_to_shared(smem + POF_B);
    uint32_t u_a2 = (uint32_t)__cvta_generic_to_shared(smem + POF_A2);
    uint32_t u_b2 = (uint32_t)__cvta_generic_to_shared(smem + POF_B2);

    int tid = threadIdx.x, lane = tid & 31, warp = tid >> 5;
    int wm = warp & 3, wn = warp >> 2;
    int id = blockIdx.x;
    int nb = id & 3;
    int jt = (id >> 2) & 31;
    int it = (id >> 7) & 15;
    int bi = id >> 11;
    int i0 = it << 4, j0 = jt << 3, n0 = nb << 7;

    if (tid < 128) {
        sBias[tid] = bs2[n0 + tid];
        sW3[tid * 2]     = Ws3[(n0 + tid) * 2];
        sW3[tid * 2 + 1] = Ws3[(n0 + tid) * 2 + 1];
        sLP[tid] = 0.f; sLP[tid + 128] = 0.f;
    }

    const __half* ga = g_a16 + (long)(bi * 256 + i0) * HID;
    const __half* gb = g_b16 + (long)(bi * 256 + j0) * HID;
    const __half* wsrc = g_ws2t + (long)n0 * HID;

    float acc[2][8][4];
    #pragma unroll
    for (int a = 0; a < 2; a++)
        #pragma unroll
        for (int b_ = 0; b_ < 8; b_++)
            #pragma unroll
            for (int c = 0; c < 4; c++) acc[a][b_][c] = 0.f;

    #define ISSUE(cc, bb) do {                                                \
        int k0h = (cc) * 64;                                                  \
        _Pragma("unroll")                                                     \
        for (int t = tid; t < 1216; t += 256) {                               \
            if (t < 1024) {                                                   \
                int n = t >> 3, seg = t & 7;                                  \
                asm volatile("cp.async.cg.shared.global [%0], [%1], 16;"      \
                    :: "r"(u_b + (bb)*18432 + n*144 + seg*16),                \
                       "l"(wsrc + (long)n*HID + k0h + seg*8) : "memory");     \
            } else if (t < 1152) {                                            \
                int u = t - 1024; int r = u >> 3, seg = u & 7;                \
                asm volatile("cp.async.ca.shared.global [%0], [%1], 16;"      \
                    :: "r"(u_a2 + (bb)*2560 + r*160 + seg*16),                \
                       "l"(ga + (long)r*HID + k0h + seg*8) : "memory");       \
            } else {                                                          \
                int u = t - 1152; int r = u >> 3, seg = u & 7;                \
                asm volatile("cp.async.ca.shared.global [%0], [%1], 16;"      \
                    :: "r"(u_b2 + (bb)*1280 + r*160 + seg*16),                \
                       "l"(gb + (long)r*HID + k0h + seg*8) : "memory");       \
            }                                                                 \
        }                                                                     \
        asm volatile("cp.async.commit_group;" ::: "memory");                  \
    } while (0)

    // prologue: chunks 0,1 in flight
    ISSUE(0, 0);
    ISSUE(1, 1);

    int c0 = lane & 3;
    int jl = lane >> 2;
    uint32_t ldm_off = (uint32_t)(wn * 64 + ((lane >> 4) << 3) + (lane & 7)) * 144u
                     + (uint32_t)((lane >> 3) & 1) * 16u;

    for (int c = 0; c < 16; c++) {
        if (c < 15) asm volatile("cp.async.wait_group 1;" ::: "memory");
        else        asm volatile("cp.async.wait_group 0;" ::: "memory");
        __syncthreads();

        int buf = c % 3;
        const unsigned* A2 = (const unsigned*)(smem + POF_A2 + buf * 2560);
        const unsigned* B2 = (const unsigned*)(smem + POF_B2 + buf * 1280);
        uint32_t bb_base = u_b + buf * 18432 + ldm_off;

        #pragma unroll
        for (int ks = 0; ks < 4; ks++) {
            uint2 bv = *(const uint2*)(B2 + jl * 40 + ks * 8 + 2 * c0);
            unsigned af[2][4], bf[8][2];
            #pragma unroll
            for (int mi = 0; mi < 2; mi++) {
                int base = (wm * 4 + mi * 2) * 40 + ks * 8 + 2 * c0;
                uint2 a01 = *(const uint2*)(A2 + base);
                uint2 a23 = *(const uint2*)(A2 + base + 40);
                af[mi][0] = addrelu2(a01.x, bv.x);
                af[mi][1] = addrelu2(a23.x, bv.x);
                af[mi][2] = addrelu2(a01.y, bv.y);
                af[mi][3] = addrelu2(a23.y, bv.y);
            }
            #pragma unroll
            for (int g = 0; g < 4; g++) {
                unsigned rr[4];
                ldm4(rr, bb_base + (uint32_t)g * 2304u + (uint32_t)ks * 32u);
                bf[g * 2][0]     = rr[0];
                bf[g * 2][1]     = rr[1];
                bf[g * 2 + 1][0] = rr[2];
                bf[g * 2 + 1][1] = rr[3];
            }
            #pragma unroll
            for (int mi = 0; mi < 2; mi++)
                #pragma unroll
                for (int nt = 0; nt < 8; nt++)
                    mma16(acc[mi][nt], af[mi], bf[nt]);
        }

        if (c + 2 < 16) ISSUE(c + 2, (c + 2) % 3);
    }
    __syncthreads();

    // ---- epilogue ----
    float lp[2][2][2];
    #pragma unroll
    for (int mi = 0; mi < 2; mi++)
        #pragma unroll
        for (int h = 0; h < 2; h++) { lp[mi][h][0] = 0.f; lp[mi][h][1] = 0.f; }

    #pragma unroll
    for (int mi = 0; mi < 2; mi++)
        #pragma unroll
        for (int nt = 0; nt < 8; nt++) {
            int cl = wn * 64 + nt * 8 + ((lane & 3) << 1);
            float bz0 = sBias[cl], bz1 = sBias[cl + 1];
            float w00 = sW3[cl * 2],       w01 = sW3[cl * 2 + 1];
            float w10 = sW3[(cl + 1) * 2], w11 = sW3[(cl + 1) * 2 + 1];
            float z0 = fmaxf(acc[mi][nt][0] + bz0, 0.f);
            float z1 = fmaxf(acc[mi][nt][1] + bz1, 0.f);
            float z2 = fmaxf(acc[mi][nt][2] + bz0, 0.f);
            float z3 = fmaxf(acc[mi][nt][3] + bz1, 0.f);
            lp[mi][0][0] += z0 * w00 + z1 * w10;
            lp[mi][0][1] += z0 * w01 + z1 * w11;
            lp[mi][1][0] += z2 * w00 + z3 * w10;
            lp[mi][1][1] += z2 * w01 + z3 * w11;
        }
    #pragma unroll
    for (int off = 1; off < 4; off <<= 1)
        #pragma unroll
        for (int mi = 0; mi < 2; mi++)
            #pragma unroll
            for (int h = 0; h < 2; h++) {
                lp[mi][h][0] += __shfl_xor_sync(0xffffffffu, lp[mi][h][0], off);
                lp[mi][h][1] += __shfl_xor_sync(0xffffffffu, lp[mi][h][1], off);
            }
    if ((lane & 3) == 0) {
        #pragma unroll
        for (int mi = 0; mi < 2; mi++) {
            int p = wm * 32 + mi * 16 + (lane >> 2);
            atomicAdd(&sLP[p * 2],           lp[mi][0][0]);
            atomicAdd(&sLP[p * 2 + 1],       lp[mi][0][1]);
            atomicAdd(&sLP[(p + 8) * 2],     lp[mi][1][0]);
            atomicAdd(&sLP[(p + 8) * 2 + 1], lp[mi][1][1]);
        }
    }
    __syncthreads();
    {
        int p = tid >> 1, s = tid & 1;
        int i = i0 + (p >> 3), j = j0 + (p & 7);
        long flat = (long)(bi * 256 + i) * 256 + j;
        atomicAdd(&g_logit[flat * 2 + s], sLP[tid]);
    }
    #undef ISSUE
}

// ---------------- fused row epilogue + last-block loss finalize -------------
__global__ void epi_row(const float* __restrict__ bs3, float* __restrict__ out)
{
    int row = blockIdx.x;
    int tid = threadIdx.x;
    int bi = row >> 8;
    int idx = row * 256 + tid;

    float l0 = g_logit[idx * 2]     + bs3[0];
    float l1 = g_logit[idx * 2 + 1] + bs3[1];
    float m = fmaxf(l0, l1);
    float e0 = expf(l0 - m), e1 = expf(l1 - m);
    float lse = m + logf(e0 + e1);
    float lq0 = l0 - lse, lq1 = l1 - lse;
    float q1 = expf(lq1);
    float sel = (g_segy[row] == g_segy[(bi << 8) + tid]) ? lq1 : lq0;

    __shared__ float sred[256][6];
    __shared__ float red[256];
    __shared__ int slast;
    const float* hp = g_hatp + (long)((bi << 8) + tid) * 6;
    #pragma unroll
    for (int c = 0; c < 6; c++) sred[tid][c] = q1 * hp[c];
    red[tid] = sel;
    __syncthreads();
    for (int s = 128; s > 0; s >>= 1) {
        if (tid < s) {
            #pragma unroll
            for (int c = 0; c < 6; c++) sred[tid][c] += sred[tid + s][c];
            red[tid] += red[tid + s];
        }
        __syncthreads();
    }
    if (tid < 6) out[1 + row * 6 + tid] = g_hatp[row * 6 + tid];
    if (tid == 0) {
        g_loss2_part[row] = red[0];
        float t = 0.f;
        #pragma unroll
        for (int c = 0; c < 6; c++) t += sred[0][c];
        #pragma unroll
        for (int c = 0; c < 6; c++) out[3073 + row * 6 + c] = sred[0][c] / t;
        __threadfence();
        slast = (atomicAdd(&g_ctr, 1) == 511);
    }
    if (tid == 32) out[6145 + row] = (float)g_segy[row];
    __syncthreads();
    if (slast) {
        __threadfence();
        float r1 = g_loss1_terms[tid] + g_loss1_terms[tid + 256];
        float r2 = g_loss2_part[tid] + g_loss2_part[tid + 256];
        red[tid] = r2;
        sred[tid][0] = r1;
        __syncthreads();
        for (int s = 128; s > 0; s >>= 1) {
            if (tid < s) { sred[tid][0] += sred[tid + s][0]; red[tid] += red[tid + s]; }
            __syncthreads();
        }
        if (tid == 0) out[0] = sred[0][0] / 512.0f - red[0] / 131072.0f;
    }
}

// ---------------- launch (R12-proven topology) ----------------
extern "C" void kernel_launch(void* const* d_in, const int* in_sizes, int n_in,
                              void* d_out, int out_size)
{
    const float* agg = (const float*)d_in[0];
    const int*   yw  = (const int*)d_in[1];
    const float* W1  = (const float*)d_in[2];
    const float* b1  = (const float*)d_in[3];
    const float* W2  = (const float*)d_in[4];
    const float* b2  = (const float*)d_in[5];
    const float* W3  = (const float*)d_in[6];
    const float* b3  = (const float*)d_in[7];
    const float* Ws1 = (const float*)d_in[8];
    const float* bs1 = (const float*)d_in[9];
    const float* Ws2 = (const float*)d_in[10];
    const float* bs2 = (const float*)d_in[11];
    const float* Ws3 = (const float*)d_in[12];
    const float* bs3 = (const float*)d_in[13];
    float* out = (float*)d_out;

    static cudaStream_t s1;
    static cudaEvent_t evF, evG, evZ, evS;
    static int cfg_done = 0;
    if (!cfg_done) {
        cudaFuncSetAttribute(pair_fp16,
                             cudaFuncAttributeMaxDynamicSharedMemorySize, PSMEM);
        cudaFuncSetAttribute(gemm3,
                             cudaFuncAttributeMaxDynamicSharedMemorySize, GSMEM);
        cudaFuncSetAttribute(gemm_h2,
                             cudaFuncAttributeMaxDynamicSharedMemorySize, GSMEM);
        cudaStreamCreateWithFlags(&s1, cudaStreamNonBlocking);
        cudaEventCreateWithFlags(&evF, cudaEventDisableTiming);
        cudaEventCreateWithFlags(&evG, cudaEventDisableTiming);
        cudaEventCreateWithFlags(&evZ, cudaEventDisableTiming);
        cudaEventCreateWithFlags(&evS, cudaEventDisableTiming);
        cfg_done = 1;
    }

    cudaEventRecord(evF, 0);
    cudaStreamWaitEvent(s1, evF, 0);

    zeroprep<<<64, 256, 0, s1>>>(Ws2);
    cudaEventRecord(evZ, s1);

    gemm3<<<96, 256, GSMEM>>>(agg, W1, b1, Ws1, bs1);
    cudaEventRecord(evG, 0);

    cudaStreamWaitEvent(s1, evG, 0);
    gemm_h2<<<128, 256, GSMEM, s1>>>(W2);
    seg_epilogue<<<512, 32, 0, s1>>>(W3, b3, b2, yw);
    cudaEventRecord(evS, s1);

    cudaStreamWaitEvent(0, evZ, 0);
    pair_fp16<<<4096, 256, PSMEM>>>(bs2, Ws3);

    cudaStreamWaitEvent(0, evS, 0);
    epi_row<<<512, 256>>>(bs3, out);
}

// round 17
// speedup vs baseline: 1.0449x; 1.0003x over previous
#include <cuda_runtime.h>
#include <cuda_fp16.h>
#include <math.h>
#include <float.h>
#include <stdint.h>

#define BDIM 2
#define NSEG 256
#define HID 1024
#define HID2 512
#define NCLS 6
#define NROWS 512
#define NPAIRS 131072

// ---------------- scratch ----------------
__device__ __half g_a16[NROWS*HID];   // k-words PERMUTED: pos 2m<->word m, 2m+1<->word m+4 (per 8-word group)
__device__ __half g_b16[NROWS*HID];   // same permutation
__device__ float g_h1[NROWS*HID];
__device__ float g_h2[NROWS*HID2];
__device__ float g_hatp[NROWS*NCLS];
__device__ float g_loss1_terms[NROWS];
__device__ int   g_segy[NROWS];
__device__ float g_logit[NPAIRS*2];
__device__ float g_loss2_part[512];
__device__ int   g_ctr;
__device__ __half g_ws2t[HID2*HID];   // unpermuted [n][k]

// ---------------- helpers ----------------
__device__ __forceinline__ unsigned f2tf32(unsigned xbits) {
    unsigned r;
    asm("cvt.rna.tf32.f32 %0, %1;" : "=r"(r) : "r"(xbits));
    return r;
}
__device__ __forceinline__ void mma8(float* d, const unsigned* a, const unsigned* b) {
    asm volatile(
        "mma.sync.aligned.m16n8k8.row.col.f32.tf32.tf32.f32 "
        "{%0,%1,%2,%3}, {%4,%5,%6,%7}, {%8,%9}, {%0,%1,%2,%3};\n"
        : "+f"(d[0]), "+f"(d[1]), "+f"(d[2]), "+f"(d[3])
        : "r"(a[0]), "r"(a[1]), "r"(a[2]), "r"(a[3]), "r"(b[0]), "r"(b[1]));
}
__device__ __forceinline__ void mma16(float* d, const unsigned* a, const unsigned* b) {
    asm volatile(
        "mma.sync.aligned.m16n8k16.row.col.f32.f16.f16.f32 "
        "{%0,%1,%2,%3}, {%4,%5,%6,%7}, {%8,%9}, {%0,%1,%2,%3};\n"
        : "+f"(d[0]), "+f"(d[1]), "+f"(d[2]), "+f"(d[3])
        : "r"(a[0]), "r"(a[1]), "r"(a[2]), "r"(a[3]), "r"(b[0]), "r"(b[1]));
}
__device__ __forceinline__ void ldm4(unsigned* r, uint32_t addr) {
    asm volatile(
        "ldmatrix.sync.aligned.m8n8.x4.shared.b16 {%0,%1,%2,%3}, [%4];"
        : "=r"(r[0]), "=r"(r[1]), "=r"(r[2]), "=r"(r[3]) : "r"(addr));
}
__device__ __forceinline__ unsigned packh2(float lo, float hi) {
    __half2 h = __floats2half2_rn(lo, hi);
    return *reinterpret_cast<unsigned*>(&h);
}
__device__ __forceinline__ unsigned addrelu2(unsigned a, unsigned b) {
    __half2 r = __hmax2(__hadd2(*(__half2*)&a, *(__half2*)&b),
                        __float2half2_rn(0.f));
    return *reinterpret_cast<unsigned*>(&r);
}

#define SA_LD 36
#define SB_LD 136
#define GOF_A   0
#define GA_ST   18432
#define GOF_B   36864
#define GB_ST   17408
#define GSMEM   71680

// ---------------- tf32 GEMM body, cp.async double-buffered (proven) ---------
__device__ __forceinline__ void gemm_body(
    const float* __restrict__ A, int lda, const float* __restrict__ B, int ldb,
    float* __restrict__ C, __half* __restrict__ Ch, int ldc,
    const float* __restrict__ bias,
    int kbeg, int kend, int m0, int n0, int mode, char* smem)
{
    int tid = threadIdx.x;
    int lane = tid & 31, warp = tid >> 5;
    int wm = warp & 3, wn = warp >> 2;
    uint32_t u_a = (uint32_t)__cvta_generic_to_shared(smem + GOF_A);
    uint32_t u_b = (uint32_t)__cvta_generic_to_shared(smem + GOF_B);

    float acc[2][8][4];
    #pragma unroll
    for (int a = 0; a < 2; a++)
        #pragma unroll
        for (int b_ = 0; b_ < 8; b_++)
            #pragma unroll
            for (int c = 0; c < 4; c++) acc[a][b_][c] = 0.f;

    int nk = (kend - kbeg) >> 5;

    #define ISSUE_G(k0v, st) do {                                             \
        int _k0 = (k0v);                                                      \
        _Pragma("unroll")                                                     \
        for (int t = tid; t < 2048; t += 256) {                               \
            if (t < 1024) {                                                   \
                int row = t >> 3, cv = (t & 7) << 2;                          \
                asm volatile("cp.async.cg.shared.global [%0], [%1], 16;"      \
                    :: "r"(u_a + (st)*GA_ST + (row*SA_LD + cv)*4),            \
                       "l"(A + (long)(m0 + row)*lda + _k0 + cv) : "memory");  \
            } else {                                                          \
                int u = t - 1024;                                             \
                int row = u >> 5, cv = (u & 31) << 2;                         \
                asm volatile("cp.async.cg.shared.global [%0], [%1], 16;"      \
                    :: "r"(u_b + (st)*GB_ST + (row*SB_LD + cv)*4),            \
                       "l"(B + (long)(_k0 + row)*ldb + n0 + cv) : "memory");  \
            }                                                                 \
        }                                                                     \
        asm volatile("cp.async.commit_group;" ::: "memory");                  \
    } while (0)

    ISSUE_G(kbeg, 0);

    for (int it = 0; it < nk; it++) {
        __syncthreads();
        if (it + 1 < nk) {
            ISSUE_G(kbeg + ((it + 1) << 5), (it + 1) & 1);
            asm volatile("cp.async.wait_group 1;" ::: "memory");
        } else {
            asm volatile("cp.async.wait_group 0;" ::: "memory");
        }
        __syncthreads();

        const unsigned* sA = (const unsigned*)(smem + GOF_A + (it & 1) * GA_ST);
        const unsigned* sB = (const unsigned*)(smem + GOF_B + (it & 1) * GB_ST);
        #pragma unroll
        for (int ks = 0; ks < 4; ks++) {
            int k = ks << 3;
            unsigned af[2][4], bf[8][2];
            #pragma unroll
            for (int mi = 0; mi < 2; mi++) {
                int r = wm * 32 + mi * 16 + (lane >> 2);
                int c = k + (lane & 3);
                af[mi][0] = f2tf32(sA[r * SA_LD + c]);
                af[mi][1] = f2tf32(sA[(r + 8) * SA_LD + c]);
                af[mi][2] = f2tf32(sA[r * SA_LD + c + 4]);
                af[mi][3] = f2tf32(sA[(r + 8) * SA_LD + c + 4]);
            }
            #pragma unroll
            for (int ni = 0; ni < 8; ni++) {
                int c = wn * 64 + ni * 8 + (lane >> 2);
                int r = k + (lane & 3);
                bf[ni][0] = f2tf32(sB[r * SB_LD + c]);
                bf[ni][1] = f2tf32(sB[(r + 4) * SB_LD + c]);
            }
            #pragma unroll
            for (int mi = 0; mi < 2; mi++)
                #pragma unroll
                for (int ni = 0; ni < 8; ni++)
                    mma8(acc[mi][ni], af[mi], bf[ni]);
        }
    }
    #undef ISSUE_G

    #pragma unroll
    for (int mi = 0; mi < 2; mi++)
        #pragma unroll
        for (int ni = 0; ni < 8; ni++) {
            int r = m0 + wm * 32 + mi * 16 + (lane >> 2);
            int c = n0 + wn * 64 + ni * 8 + ((lane & 3) << 1);
            if (mode == 2) {
                atomicAdd(&C[(long)r * ldc + c],           acc[mi][ni][0]);
                atomicAdd(&C[(long)r * ldc + c + 1],       acc[mi][ni][1]);
                atomicAdd(&C[(long)(r + 8) * ldc + c],     acc[mi][ni][2]);
                atomicAdd(&C[(long)(r + 8) * ldc + c + 1], acc[mi][ni][3]);
            } else {
                float b0 = bias ? bias[c] : 0.f;
                float b1 = bias ? bias[c + 1] : 0.f;
                float v0 = acc[mi][ni][0] + b0, v1 = acc[mi][ni][1] + b1;
                float v2 = acc[mi][ni][2] + b0, v3 = acc[mi][ni][3] + b1;
                if (mode == 1) {
                    v0 = fmaxf(v0, 0.f); v1 = fmaxf(v1, 0.f);
                    v2 = fmaxf(v2, 0.f); v3 = fmaxf(v3, 0.f);
                    C[(long)r * ldc + c]       = v0; C[(long)r * ldc + c + 1]       = v1;
                    C[(long)(r + 8) * ldc + c] = v2; C[(long)(r + 8) * ldc + c + 1] = v3;
                } else {
                    // permuted k-word storage: word w -> pos (w&~7)|((w&3)<<1)|((w>>2)&1)
                    int w = c >> 1;
                    int wp = (w & ~7) | ((w & 3) << 1) | ((w >> 2) & 1);
                    *(unsigned*)&Ch[(long)r * ldc + wp * 2]       = packh2(v0, v1);
                    *(unsigned*)&Ch[(long)(r + 8) * ldc + wp * 2] = packh2(v2, v3);
                }
            }
        }
}

// h1 / a16 / b16 fused: 24 roles x 4 m-tiles = 96 CTAs.
__global__ __launch_bounds__(256)
void gemm3(const float* __restrict__ agg,
           const float* __restrict__ W1, const float* __restrict__ b1,
           const float* __restrict__ Ws1, const float* __restrict__ bs1)
{
    extern __shared__ char smem[];
    int tn = blockIdx.x % 24;
    int m0 = (blockIdx.x / 24) << 7;
    int grp = tn >> 3;
    int n0 = (tn & 7) << 7;
    if (grp == 0)
        gemm_body(agg, 512, W1, 1024, g_h1, (half*)0, 1024, b1, 0, 512, m0, n0, 1, smem);
    else if (grp == 1)
        gemm_body(agg, 512, Ws1, 1024, (float*)0, g_a16, 1024, bs1, 0, 512, m0, n0, 3, smem);
    else
        gemm_body(agg, 512, Ws1 + 512 * 1024, 1024, (float*)0, g_b16, 1024,
                  (const float*)0, 0, 512, m0, n0, 3, smem);
}

__global__ __launch_bounds__(256)
void gemm_h2(const float* __restrict__ W2)
{
    extern __shared__ char smem[];
    int t = blockIdx.x & 15;
    int ks = blockIdx.x >> 4;
    int m0 = (t >> 2) << 7;
    int n0 = (t & 3) << 7;
    gemm_body(g_h1, 1024, W2, 512, g_h2, (half*)0, 512, (const float*)0,
              ks * 128, ks * 128 + 128, m0, n0, 2, smem);
}

// ---------------- fused: zero bufs + counter + Ws2 transpose->fp16 ----------
__global__ void zeroprep(const float* __restrict__ Ws2)
{
    int tid = threadIdx.x;
    if (blockIdx.x < 32) {
        if (blockIdx.x == 0 && tid == 0) g_ctr = 0;
        int base = blockIdx.x * 16384 + tid;
        #pragma unroll
        for (int r = 0; r < 64; r++) {
            int i = base + r * 256;
            if (i < NPAIRS * 2) g_logit[i] = 0.f;
            else g_h2[i - NPAIRS * 2] = 0.f;
        }
    } else {
        __shared__ float tile[32][33];
        int tx = tid & 31, ty = tid >> 5;
        int tbase = (blockIdx.x - 32) * 16;
        for (int t = 0; t < 16; t++) {
            int bx = (tbase + t) & 15;
            int by = (tbase + t) >> 4;
            #pragma unroll
            for (int r = 0; r < 32; r += 8)
                tile[ty + r][tx] = Ws2[(long)(by * 32 + ty + r) * HID2 + bx * 32 + tx];
            __syncthreads();
            #pragma unroll
            for (int r = 0; r < 32; r += 8)
                g_ws2t[(long)(bx * 32 + ty + r) * HID + by * 32 + tx] =
                    __float2half_rn(tile[tx][ty + r]);
            __syncthreads();
        }
    }
}

// ---------------- per-segment epilogue ----------------
__global__ void seg_epilogue(const float* __restrict__ W3,
                             const float* __restrict__ b3,
                             const float* __restrict__ b2,
                             const int* __restrict__ yw)
{
    int row = blockIdx.x;
    int lane = threadIdx.x;
    float s[6] = {0.f, 0.f, 0.f, 0.f, 0.f, 0.f};
    const float* hrow = g_h2 + (long)row * HID2;
    for (int k = lane; k < HID2; k += 32) {
        float h = fmaxf(hrow[k] + b2[k], 0.f);
        const float* w = W3 + k * 6;
        #pragma unroll
        for (int c = 0; c < 6; c++) s[c] += h * w[c];
    }
    #pragma unroll
    for (int off = 16; off > 0; off >>= 1)
        #pragma unroll
        for (int c = 0; c < 6; c++) s[c] += __shfl_xor_sync(0xffffffffu, s[c], off);

    if (lane == 0) {
        float l[6], m = -FLT_MAX;
        #pragma unroll
        for (int c = 0; c < 6; c++) { l[c] = s[c] + b3[c]; m = fmaxf(m, l[c]); }
        float se = 0.f;
        #pragma unroll
        for (int c = 0; c < 6; c++) se += expf(l[c] - m);
        float lse = m + logf(se);
        #pragma unroll
        for (int c = 0; c < 6; c++) g_hatp[row * 6 + c] = expf(l[c] - lse);

        int sum12 = 0;
        #pragma unroll
        for (int w = 0; w < 12; w++) sum12 += yw[w];
        int is64 = (sum12 == 1);
        int arg = 0;
        int bv = is64 ? yw[(row * 6) * 2] : yw[row * 6];
        #pragma unroll
        for (int c = 1; c < 6; c++) {
            int v = is64 ? yw[(row * 6 + c) * 2] : yw[row * 6 + c];
            if (v > bv) { bv = v; arg = c; }
        }
        g_segy[row] = arg;
        g_loss1_terms[row] = -(l[arg] - lse);
    }
}

// ---------------- fp16 pairwise GEMM: ldmatrix B + uint2 cache loads --------
// a/b caches: 160B pitch (40 u32), permuted k-words -> (c0,c0+4) adjacent.
#define POF_B    0                        // 3 x 18432 = 55296
#define POF_A2   55296                    // 3 x 2560  = 7680 (16 rows x 160B)
#define POF_B2   62976                    // 3 x 1280  = 3840 (8 rows x 160B)
#define POF_BIAS 66816
#define POF_W3   67328
#define POF_LP   68352
#define PSMEM    69376

__global__ void __launch_bounds__(256, 2)
pair_fp16(const float* __restrict__ bs2, const float* __restrict__ Ws3)
{
    extern __shared__ char smem[];
    float* sBias = (float*)(smem + POF_BIAS);
    float* sW3   = (float*)(smem + POF_W3);
    float* sLP   = (float*)(smem + POF_LP);

    uint32_t u_b  = (uint32_t)__cvta_generic_to_shared(smem + POF_B);
    uint32_t u_a2 = (uint32_t)__cvta_generic_to_shared(smem + POF_A2);
    uint32_t u_b2 = (uint32_t)__cvta_generic_to_shared(smem + POF_B2);

    int tid = threadIdx.x, lane = tid & 31, warp = tid >> 5;
    int wm = warp & 3, wn = warp >> 2;
    int id = blockIdx.x;
    int nb = id & 3;
    int jt = (id >> 2) & 31;
    int it = (id >> 7) & 15;
    int bi = id >> 11;
    int i0 = it << 4, j0 = jt << 3, n0 = nb << 7;

    if (tid < 128) {
        sBias[tid] = bs2[n0 + tid];
        sW3[tid * 2]     = Ws3[(n0 + tid) * 2];
        sW3[tid * 2 + 1] = Ws3[(n0 + tid) * 2 + 1];
        sLP[tid] = 0.f; sLP[tid + 128] = 0.f;
    }

    const __half* ga = g_a16 + (long)(bi * 256 + i0) * HID;
    const __half* gb = g_b16 + (long)(bi * 256 + j0) * HID;
    const __half* wsrc = g_ws2t + (long)n0 * HID;

    float acc[2][8][4];
    #pragma unroll
    for (int a = 0; a < 2; a++)
        #pragma unroll
        for (int b_ = 0; b_ < 8; b_++)
            #pragma unroll
            for (int c = 0; c < 4; c++) acc[a][b_][c] = 0.f;

    #define ISSUE(cc, bb) do {                                                \
        int k0h = (cc) * 64;                                                  \
        _Pragma("unroll")                                                     \
        for (int t = tid; t < 1216; t += 256) {                               \
            if (t < 1024) {                                                   \
                int n = t >> 3, seg = t & 7;                                  \
                asm volatile("cp.async.cg.shared.global [%0], [%1], 16;"      \
                    :: "r"(u_b + (bb)*18432 + n*144 + seg*16),                \
                       "l"(wsrc + (long)n*HID + k0h + seg*8) : "memory");     \
            } else if (t < 1152) {                                            \
                int u = t - 1024; int r = u >> 3, seg = u & 7;                \
                asm volatile("cp.async.ca.shared.global [%0], [%1], 16;"      \
                    :: "r"(u_a2 + (bb)*2560 + r*160 + seg*16),                \
                       "l"(ga + (long)r*HID + k0h + seg*8) : "memory");       \
            } else {                                                          \
                int u = t - 1152; int r = u >> 3, seg = u & 7;                \
                asm volatile("cp.async.ca.shared.global [%0], [%1], 16;"      \
                    :: "r"(u_b2 + (bb)*1280 + r*160 + seg*16),                \
                       "l"(gb + (long)r*HID + k0h + seg*8) : "memory");       \
            }                                                                 \
        }                                                                     \
        asm volatile("cp.async.commit_group;" ::: "memory");                  \
    } while (0)

    // prologue: chunks 0,1 in flight
    ISSUE(0, 0);
    ISSUE(1, 1);

    int c0 = lane & 3;
    int jl = lane >> 2;
    uint32_t ldm_off = (uint32_t)(wn * 64 + ((lane >> 4) << 3) + (lane & 7)) * 144u
                     + (uint32_t)((lane >> 3) & 1) * 16u;

    for (int c = 0; c < 16; c++) {
        if (c < 15) asm volatile("cp.async.wait_group 1;" ::: "memory");
        else        asm volatile("cp.async.wait_group 0;" ::: "memory");
        __syncthreads();

        int buf = c % 3;
        const unsigned* A2 = (const unsigned*)(smem + POF_A2 + buf * 2560);
        const unsigned* B2 = (const unsigned*)(smem + POF_B2 + buf * 1280);
        uint32_t bb_base = u_b + buf * 18432 + ldm_off;

        #pragma unroll
        for (int ks = 0; ks < 4; ks++) {
            uint2 bv = *(const uint2*)(B2 + jl * 40 + ks * 8 + 2 * c0);
            unsigned af[2][4], bf[8][2];
            #pragma unroll
            for (int mi = 0; mi < 2; mi++) {
                int base = (wm * 4 + mi * 2) * 40 + ks * 8 + 2 * c0;
                uint2 a01 = *(const uint2*)(A2 + base);
                uint2 a23 = *(const uint2*)(A2 + base + 40);
                af[mi][0] = addrelu2(a01.x, bv.x);
                af[mi][1] = addrelu2(a23.x, bv.x);
                af[mi][2] = addrelu2(a01.y, bv.y);
                af[mi][3] = addrelu2(a23.y, bv.y);
            }
            #pragma unroll
            for (int g = 0; g < 4; g++) {
                unsigned rr[4];
                ldm4(rr, bb_base + (uint32_t)g * 2304u + (uint32_t)ks * 32u);
                bf[g * 2][0]     = rr[0];
                bf[g * 2][1]     = rr[1];
                bf[g * 2 + 1][0] = rr[2];
                bf[g * 2 + 1][1] = rr[3];
            }
            #pragma unroll
            for (int mi = 0; mi < 2; mi++)
                #pragma unroll
                for (int nt = 0; nt < 8; nt++)
                    mma16(acc[mi][nt], af[mi], bf[nt]);
        }

        if (c + 2 < 16) ISSUE(c + 2, (c + 2) % 3);
    }
    __syncthreads();

    // ---- epilogue ----
    float lp[2][2][2];
    #pragma unroll
    for (int mi = 0; mi < 2; mi++)
        #pragma unroll
        for (int h = 0; h < 2; h++) { lp[mi][h][0] = 0.f; lp[mi][h][1] = 0.f; }

    #pragma unroll
    for (int mi = 0; mi < 2; mi++)
        #pragma unroll
        for (int nt = 0; nt < 8; nt++) {
            int cl = wn * 64 + nt * 8 + ((lane & 3) << 1);
            float bz0 = sBias[cl], bz1 = sBias[cl + 1];
            float w00 = sW3[cl * 2],       w01 = sW3[cl * 2 + 1];
            float w10 = sW3[(cl + 1) * 2], w11 = sW3[(cl + 1) * 2 + 1];
            float z0 = fmaxf(acc[mi][nt][0] + bz0, 0.f);
            float z1 = fmaxf(acc[mi][nt][1] + bz1, 0.f);
            float z2 = fmaxf(acc[mi][nt][2] + bz0, 0.f);
            float z3 = fmaxf(acc[mi][nt][3] + bz1, 0.f);
            lp[mi][0][0] += z0 * w00 + z1 * w10;
            lp[mi][0][1] += z0 * w01 + z1 * w11;
            lp[mi][1][0] += z2 * w00 + z3 * w10;
            lp[mi][1][1] += z2 * w01 + z3 * w11;
        }
    #pragma unroll
    for (int off = 1; off < 4; off <<= 1)
        #pragma unroll
        for (int mi = 0; mi < 2; mi++)
            #pragma unroll
            for (int h = 0; h < 2; h++) {
                lp[mi][h][0] += __shfl_xor_sync(0xffffffffu, lp[mi][h][0], off);
                lp[mi][h][1] += __shfl_xor_sync(0xffffffffu, lp[mi][h][1], off);
            }
    if ((lane & 3) == 0) {
        #pragma unroll
        for (int mi = 0; mi < 2; mi++) {
            int p = wm * 32 + mi * 16 + (lane >> 2);
            atomicAdd(&sLP[p * 2],           lp[mi][0][0]);
            atomicAdd(&sLP[p * 2 + 1],       lp[mi][0][1]);
            atomicAdd(&sLP[(p + 8) * 2],     lp[mi][1][0]);
            atomicAdd(&sLP[(p + 8) * 2 + 1], lp[mi][1][1]);
        }
    }
    __syncthreads();
    {
        int p = tid >> 1, s = tid & 1;
        int i = i0 + (p >> 3), j = j0 + (p & 7);
        long flat = (long)(bi * 256 + i) * 256 + j;
        atomicAdd(&g_logit[flat * 2 + s], sLP[tid]);
    }
    #undef ISSUE
}

// ---------------- fused row epilogue + last-block loss finalize -------------
__global__ void epi_row(const float* __restrict__ bs3, float* __restrict__ out)
{
    int row = blockIdx.x;
    int tid = threadIdx.x;
    int bi = row >> 8;
    int idx = row * 256 + tid;

    float l0 = g_logit[idx * 2]     + bs3[0];
    float l1 = g_logit[idx * 2 + 1] + bs3[1];
    float m = fmaxf(l0, l1);
    float e0 = expf(l0 - m), e1 = expf(l1 - m);
    float lse = m + logf(e0 + e1);
    float lq0 = l0 - lse, lq1 = l1 - lse;
    float q1 = expf(lq1);
    float sel = (g_segy[row] == g_segy[(bi << 8) + tid]) ? lq1 : lq0;

    __shared__ float sred[256][6];
    __shared__ float red[256];
    __shared__ int slast;
    const float* hp = g_hatp + (long)((bi << 8) + tid) * 6;
    #pragma unroll
    for (int c = 0; c < 6; c++) sred[tid][c] = q1 * hp[c];
    red[tid] = sel;
    __syncthreads();
    for (int s = 128; s > 0; s >>= 1) {
        if (tid < s) {
            #pragma unroll
            for (int c = 0; c < 6; c++) sred[tid][c] += sred[tid + s][c];
            red[tid] += red[tid + s];
        }
        __syncthreads();
    }
    if (tid < 6) out[1 + row * 6 + tid] = g_hatp[row * 6 + tid];
    if (tid == 0) {
        g_loss2_part[row] = red[0];
        float t = 0.f;
        #pragma unroll
        for (int c = 0; c < 6; c++) t += sred[0][c];
        #pragma unroll
        for (int c = 0; c < 6; c++) out[3073 + row * 6 + c] = sred[0][c] / t;
        __threadfence();
        slast = (atomicAdd(&g_ctr, 1) == 511);
    }
    if (tid == 32) out[6145 + row] = (float)g_segy[row];
    __syncthreads();
    if (slast) {
        __threadfence();
        float r1 = g_loss1_terms[tid] + g_loss1_terms[tid + 256];
        float r2 = g_loss2_part[tid] + g_loss2_part[tid + 256];
        red[tid] = r2;
        sred[tid][0] = r1;
        __syncthreads();
        for (int s = 128; s > 0; s >>= 1) {
            if (tid < s) { sred[tid][0] += sred[tid + s][0]; red[tid] += red[tid + s]; }
            __syncthreads();
        }
        if (tid == 0) out[0] = sred[0][0] / 512.0f - red[0] / 131072.0f;
    }
}

// ---------------- launch (proven topology) ----------------
extern "C" void kernel_launch(void* const* d_in, const int* in_sizes, int n_in,
                              void* d_out, int out_size)
{
    const float* agg = (const float*)d_in[0];
    const int*   yw  = (const int*)d_in[1];
    const float* W1  = (const float*)d_in[2];
    const float* b1  = (const float*)d_in[3];
    const float* W2  = (const float*)d_in[4];
    const float* b2  = (const float*)d_in[5];
    const float* W3  = (const float*)d_in[6];
    const float* b3  = (const float*)d_in[7];
    const float* Ws1 = (const float*)d_in[8];
    const float* bs1 = (const float*)d_in[9];
    const float* Ws2 = (const float*)d_in[10];
    const float* bs2 = (const float*)d_in[11];
    const float* Ws3 = (const float*)d_in[12];
    const float* bs3 = (const float*)d_in[13];
    float* out = (float*)d_out;

    static cudaStream_t s1;
    static cudaEvent_t evF, evG, evZ, evS;
    static int cfg_done = 0;
    if (!cfg_done) {
        cudaFuncSetAttribute(pair_fp16,
                             cudaFuncAttributeMaxDynamicSharedMemorySize, PSMEM);
        cudaFuncSetAttribute(gemm3,
                             cudaFuncAttributeMaxDynamicSharedMemorySize, GSMEM);
        cudaFuncSetAttribute(gemm_h2,
                             cudaFuncAttributeMaxDynamicSharedMemorySize, GSMEM);
        cudaStreamCreateWithFlags(&s1, cudaStreamNonBlocking);
        cudaEventCreateWithFlags(&evF, cudaEventDisableTiming);
        cudaEventCreateWithFlags(&evG, cudaEventDisableTiming);
        cudaEventCreateWithFlags(&evZ, cudaEventDisableTiming);
        cudaEventCreateWithFlags(&evS, cudaEventDisableTiming);
        cfg_done = 1;
    }

    cudaEventRecord(evF, 0);
    cudaStreamWaitEvent(s1, evF, 0);

    zeroprep<<<64, 256, 0, s1>>>(Ws2);
    cudaEventRecord(evZ, s1);

    gemm3<<<96, 256, GSMEM>>>(agg, W1, b1, Ws1, bs1);
    cudaEventRecord(evG, 0);

    cudaStreamWaitEvent(s1, evG, 0);
    gemm_h2<<<128, 256, GSMEM, s1>>>(W2);
    seg_epilogue<<<512, 32, 0, s1>>>(W3, b3, b2, yw);
    cudaEventRecord(evS, s1);

    cudaStreamWaitEvent(0, evZ, 0);
    pair_fp16<<<4096, 256, PSMEM>>>(bs2, Ws3);

    cudaStreamWaitEvent(0, evS, 0);
    epi_row<<<512, 256>>>(bs3, out);
}